// round 1
// baseline (speedup 1.0000x reference)
#include <cuda_runtime.h>
#include <math.h>

#define BATCH 8
#define NPTS 2048
#define NTOT (BATCH*NPTS)
#define CH 128
#define KNN 16
#define HID 32
#define EPSV 1e-6f

// ---------------- scratch (static device globals; no dynamic allocation) ----
__device__ float g_Q[NTOT*CH*3];
__device__ float g_K[NTOT*CH*3];
__device__ float g_U[NTOT*CH*3];
__device__ float g_Wt[3*CH*CH];      // transposed weights, layout [w][c][o]
__device__ int   g_idx[NTOT*KNN];    // global neighbor index (b*NPTS + j)
__device__ float g_dist[NTOT*KNN];
__device__ float g_qn[NTOT];
__device__ float g_kn[NTOT];

// ---------------- weight transpose: W[o][c] -> Wt[c][o] (coalesced GEMM reads)
__global__ void transpose_w_kernel(const float* __restrict__ Wq,
                                   const float* __restrict__ Wk,
                                   const float* __restrict__ Wu) {
    int i = blockIdx.x * 256 + threadIdx.x;       // i = o*128 + c
    if (i >= CH*CH) return;
    int o = i >> 7, c = i & 127;
    g_Wt[0*CH*CH + c*CH + o] = Wq[i];
    g_Wt[1*CH*CH + c*CH + o] = Wk[i];
    g_Wt[2*CH*CH + c*CH + o] = Wu[i];
}

// ---------------- KNN: warp per query, per-lane sorted top-16, warp merge ---
__global__ __launch_bounds__(256) void knn_kernel(const float* __restrict__ x) {
    __shared__ float sx[NPTS*3];   // 24 KB
    __shared__ float ssq[NPTS];    //  8 KB
    int b  = blockIdx.x >> 8;              // 256 blocks per batch
    int n0 = (blockIdx.x & 255) << 3;      // 8 queries per block (1 per warp)
    const float* xb = x + (size_t)b * NPTS * 3;
    for (int i = threadIdx.x; i < NPTS*3; i += 256) sx[i] = xb[i];
    __syncthreads();
    for (int i = threadIdx.x; i < NPTS; i += 256) {
        float a = sx[3*i], bb = sx[3*i+1], c = sx[3*i+2];
        ssq[i] = a*a + bb*bb + c*c;
    }
    __syncthreads();

    int warp = threadIdx.x >> 5, lane = threadIdx.x & 31;
    int n = n0 + warp;
    float qx = sx[3*n], qy = sx[3*n+1], qz = sx[3*n+2];
    float qs = ssq[n];

    float bd[KNN]; int bi[KNN];
#pragma unroll
    for (int t = 0; t < KNN; t++) { bd[t] = INFINITY; bi[t] = 0x7fffffff; }

    for (int j = lane; j < NPTS; j += 32) {
        float dot = qx*sx[3*j] + qy*sx[3*j+1] + qz*sx[3*j+2];
        float d2 = (qs + ssq[j]) - 2.f*dot;      // same formula as reference
        d2 = fmaxf(d2, 0.f);
        if (j == n) d2 = INFINITY;               // exclude self
        if (d2 < bd[KNN-1]) {
            bool placed = false;
#pragma unroll
            for (int t = KNN-1; t >= 1; t--) {
                if (!placed) {
                    if (d2 < bd[t-1]) { bd[t] = bd[t-1]; bi[t] = bi[t-1]; }
                    else              { bd[t] = d2;      bi[t] = j; placed = true; }
                }
            }
            if (!placed) { bd[0] = d2; bi[0] = j; }
        }
    }

    // merge: 16 rounds of warp-wide lexicographic (d2, idx) min
    int myj = 0;
    for (int r = 0; r < KNN; r++) {
        unsigned long long key =
            (((unsigned long long)__float_as_uint(bd[0])) << 32) | (unsigned)bi[0];
        unsigned long long mn = key;
#pragma unroll
        for (int s = 16; s > 0; s >>= 1) {
            unsigned long long o = __shfl_xor_sync(0xffffffffu, mn, s);
            mn = (o < mn) ? o : mn;
        }
        if (lane == r) myj = (int)(unsigned)(mn & 0xffffffffu);
        if (key == mn) {
#pragma unroll
            for (int t = 0; t < KNN-1; t++) { bd[t] = bd[t+1]; bi[t] = bi[t+1]; }
            bd[KNN-1] = INFINITY; bi[KNN-1] = 0x7fffffff;
        }
    }

    if (lane < KNN) {
        int j = myj;
        float dx = qx - sx[3*j], dy = qy - sx[3*j+1], dz = qz - sx[3*j+2];
        int gi = ((b << 11) + n) * KNN + lane;
        g_idx[gi]  = (b << 11) + j;
        g_dist[gi] = sqrtf(dx*dx + dy*dy + dz*dz);
    }
}

// ---------------- GEMM: Q/K/U = W{q,k,u} @ v, 8 points per block -----------
__global__ __launch_bounds__(256) void gemm_kernel(const float* __restrict__ v) {
    __shared__ float sv[8*CH*3];   // 12 KB, v for 8 points
    int p0 = blockIdx.x << 3;
    const float* vb = v + (size_t)p0 * (CH*3);
    for (int i = threadIdx.x; i < 8*CH*3; i += 256) sv[i] = vb[i];
    __syncthreads();

    int o = threadIdx.x & 127;
    int h = threadIdx.x >> 7;      // half: points h*4 .. h*4+3
    float acc[4][9];
#pragma unroll
    for (int p = 0; p < 4; p++)
#pragma unroll
        for (int q = 0; q < 9; q++) acc[p][q] = 0.f;

    const float* wq = g_Wt + o;
    const float* wk = g_Wt + CH*CH + o;
    const float* wu = g_Wt + 2*CH*CH + o;
    const float* svp = sv + h*4*(CH*3);

#pragma unroll 4
    for (int c = 0; c < CH; c++) {
        float aq = __ldg(wq + (c << 7));
        float ak = __ldg(wk + (c << 7));
        float au = __ldg(wu + (c << 7));
#pragma unroll
        for (int p = 0; p < 4; p++) {
            float vx = svp[p*384 + c*3 + 0];
            float vy = svp[p*384 + c*3 + 1];
            float vz = svp[p*384 + c*3 + 2];
            acc[p][0] = fmaf(aq, vx, acc[p][0]);
            acc[p][1] = fmaf(aq, vy, acc[p][1]);
            acc[p][2] = fmaf(aq, vz, acc[p][2]);
            acc[p][3] = fmaf(ak, vx, acc[p][3]);
            acc[p][4] = fmaf(ak, vy, acc[p][4]);
            acc[p][5] = fmaf(ak, vz, acc[p][5]);
            acc[p][6] = fmaf(au, vx, acc[p][6]);
            acc[p][7] = fmaf(au, vy, acc[p][7]);
            acc[p][8] = fmaf(au, vz, acc[p][8]);
        }
    }
#pragma unroll
    for (int p = 0; p < 4; p++) {
        size_t base = ((size_t)(p0 + h*4 + p)) * (CH*3) + o*3;
        g_Q[base+0] = acc[p][0]; g_Q[base+1] = acc[p][1]; g_Q[base+2] = acc[p][2];
        g_K[base+0] = acc[p][3]; g_K[base+1] = acc[p][4]; g_K[base+2] = acc[p][5];
        g_U[base+0] = acc[p][6]; g_U[base+1] = acc[p][7]; g_U[base+2] = acc[p][8];
    }
}

// ---------------- per-point mean channel norms of Q and K -------------------
__global__ __launch_bounds__(128) void norms_kernel() {
    int n = blockIdx.x, o = threadIdx.x;
    size_t base = (size_t)n*384 + o*3;
    float a = g_Q[base], bq = g_Q[base+1], cq = g_Q[base+2];
    float nq = sqrtf(a*a + bq*bq + cq*cq);
    float ak = g_K[base], bk = g_K[base+1], ck = g_K[base+2];
    float nk = sqrtf(ak*ak + bk*bk + ck*ck);
    __shared__ float sq[4], sk[4];
#pragma unroll
    for (int s = 16; s > 0; s >>= 1) {
        nq += __shfl_xor_sync(0xffffffffu, nq, s);
        nk += __shfl_xor_sync(0xffffffffu, nk, s);
    }
    if ((o & 31) == 0) { sq[o>>5] = nq; sk[o>>5] = nk; }
    __syncthreads();
    if (o == 0) {
        g_qn[n] = (sq[0]+sq[1]+sq[2]+sq[3]) * (1.f/128.f);
        g_kn[n] = (sk[0]+sk[1]+sk[2]+sk[3]) * (1.f/128.f);
    }
}

// ---------------- attention + message + vn layer norm + clamp ---------------
__global__ __launch_bounds__(128) void attn_kernel(
    const float* __restrict__ W1, const float* __restrict__ b1,
    const float* __restrict__ W2, const float* __restrict__ b2,
    const float* __restrict__ W3, const float* __restrict__ b3,
    const float* __restrict__ gamma, const float* __restrict__ beta,
    float* __restrict__ out) {
    int n = blockIdx.x;
    int tid = threadIdx.x;
    int lane = tid & 31, wid = tid >> 5;

    __shared__ float sW1[HID*4], sb1[HID], sW2[HID*HID], sb2[HID], sW3[HID];
    __shared__ float sqn, sb3;
    __shared__ int   sidx[KNN];
    __shared__ float skn[KNN], sdist[KNN], sdot[KNN], satt[KNN];
    __shared__ float sh1[KNN][HID];
    __shared__ float sh2[KNN][HID];
    __shared__ float swred[4][KNN];
    __shared__ float sred[4];

    for (int i = tid; i < HID*4;   i += 128) sW1[i] = W1[i];
    for (int i = tid; i < HID*HID; i += 128) sW2[i] = W2[i];
    if (tid < HID) { sb1[tid] = b1[tid]; sb2[tid] = b2[tid]; sW3[tid] = W3[tid]; }
    if (tid == 0)  { sb3 = b3[0]; sqn = g_qn[n]; }
    if (tid < KNN) {
        int j = g_idx[n*KNN + tid];
        sidx[tid]  = j;
        skn[tid]   = g_kn[j];
        sdist[tid] = g_dist[n*KNN + tid];
    }
    __syncthreads();

    size_t qb = (size_t)n*384 + tid*3;
    float qx = g_Q[qb], qy = g_Q[qb+1], qz = g_Q[qb+2];

    // dot_nbr[k] = mean_o ( Q[o,:] . K_nbr[k][o,:] )
    float part[KNN];
#pragma unroll
    for (int k = 0; k < KNN; k++) {
        const float* Kp = g_K + (size_t)sidx[k]*384 + tid*3;
        part[k] = qx*Kp[0] + qy*Kp[1] + qz*Kp[2];
    }
#pragma unroll
    for (int k = 0; k < KNN; k++) {
        float v = part[k];
#pragma unroll
        for (int s = 16; s > 0; s >>= 1) v += __shfl_xor_sync(0xffffffffu, v, s);
        if (lane == 0) swred[wid][k] = v;
    }
    __syncthreads();
    if (tid < KNN)
        sdot[tid] = (swred[0][tid]+swred[1][tid]+swred[2][tid]+swred[3][tid]) * (1.f/128.f);
    __syncthreads();

    // edge MLP layer 1: 16 edges x 32 units over 512 = 128 threads x 4
#pragma unroll
    for (int r = 0; r < 4; r++) {
        int m = tid + 128*r;
        int k = m >> 5, u = m & 31;
        float hv = sb1[u] + sW1[u*4+0]*sqn + sW1[u*4+1]*skn[k]
                          + sW1[u*4+2]*sdot[k] + sW1[u*4+3]*sdist[k];
        sh1[k][u] = hv / (1.f + expf(-hv));        // silu
    }
    __syncthreads();
    // layer 2
#pragma unroll
    for (int r = 0; r < 4; r++) {
        int m = tid + 128*r;
        int k = m >> 5, u = m & 31;
        float hv = sb2[u];
#pragma unroll
        for (int i = 0; i < HID; i++) hv = fmaf(sW2[u*32+i], sh1[k][i], hv);
        sh2[k][u] = hv / (1.f + expf(-hv));
    }
    __syncthreads();
    // layer 3 + clip
    if (tid < KNN) {
        float l = sb3;
#pragma unroll
        for (int i = 0; i < HID; i++) l = fmaf(sW3[i], sh2[tid][i], l);
        l = fminf(fmaxf(l, -10.f), 10.f);
        satt[tid] = l;
    }
    __syncthreads();
    // softmax over 16 (serial, tiny)
    if (tid == 0) {
        float mx = -1e30f;
        for (int k = 0; k < KNN; k++) mx = fmaxf(mx, satt[k]);
        float e[KNN], sum = 0.f;
        for (int k = 0; k < KNN; k++) { e[k] = expf(satt[k]-mx); sum += e[k]; }
        float inv = 1.f/sum;
        for (int k = 0; k < KNN; k++) satt[k] = e[k]*inv;
    }
    __syncthreads();

    // message
    float mxs = 0.f, mys = 0.f, mzs = 0.f;
#pragma unroll
    for (int k = 0; k < KNN; k++) {
        const float* Up = g_U + (size_t)sidx[k]*384 + tid*3;
        float a = satt[k];
        mxs = fmaf(a, Up[0], mxs);
        mys = fmaf(a, Up[1], mys);
        mzs = fmaf(a, Up[2], mzs);
    }
    float ox = qx + 0.5f*mxs;
    float oy = qy + 0.5f*mys;
    float oz = qz + 0.5f*mzs;

    // vn layer norm
    float nrm = fmaxf(sqrtf(ox*ox + oy*oy + oz*oz), EPSV);
    float v = nrm;
#pragma unroll
    for (int s = 16; s > 0; s >>= 1) v += __shfl_xor_sync(0xffffffffu, v, s);
    if (lane == 0) sred[wid] = v;
    __syncthreads();
    float mean = (sred[0]+sred[1]+sred[2]+sred[3]) * (1.f/128.f);
    __syncthreads();
    float dev = nrm - mean;
    v = dev*dev;
#pragma unroll
    for (int s = 16; s > 0; s >>= 1) v += __shfl_xor_sync(0xffffffffu, v, s);
    if (lane == 0) sred[wid] = v;
    __syncthreads();
    float stdv = fmaxf(sqrtf((sred[0]+sred[1]+sred[2]+sred[3]) * (1.f/127.f)), EPSV);
    float ns = (dev/stdv)*gamma[tid] + beta[tid];
    float sc = fmaxf(ns, EPSV) / nrm;
    ox *= sc; oy *= sc; oz *= sc;

    // clamp to max norm 50
    float n2 = fmaxf(sqrtf(ox*ox + oy*oy + oz*oz), EPSV);
    float cl = fminf(50.f/n2, 1.f);
    size_t ob = (size_t)n*384 + tid*3;
    out[ob+0] = ox*cl; out[ob+1] = oy*cl; out[ob+2] = oz*cl;
}

// ---------------- launch ----------------------------------------------------
extern "C" void kernel_launch(void* const* d_in, const int* in_sizes, int n_in,
                              void* d_out, int out_size) {
    const float* x     = (const float*)d_in[0];
    const float* v     = (const float*)d_in[1];
    const float* Wq    = (const float*)d_in[2];
    const float* Wk    = (const float*)d_in[3];
    const float* Wu    = (const float*)d_in[4];
    const float* W1    = (const float*)d_in[5];
    const float* b1    = (const float*)d_in[6];
    const float* W2    = (const float*)d_in[7];
    const float* b2    = (const float*)d_in[8];
    const float* W3    = (const float*)d_in[9];
    const float* b3    = (const float*)d_in[10];
    const float* gamma = (const float*)d_in[11];
    const float* beta  = (const float*)d_in[12];
    float* out = (float*)d_out;

    transpose_w_kernel<<<64, 256>>>(Wq, Wk, Wu);
    knn_kernel<<<2048, 256>>>(x);
    gemm_kernel<<<2048, 256>>>(v);
    norms_kernel<<<NTOT, 128>>>();
    attn_kernel<<<NTOT, 128>>>(W1, b1, W2, b2, W3, b3, gamma, beta, out);
}